// round 1
// baseline (speedup 1.0000x reference)
#include <cuda_runtime.h>
#include <cstdint>
#include <math.h>

// Problem constants: N=9 board, C=81 cells.
#define CC 81

// ---------------------------------------------------------------------------
// Scratch in __device__ globals (no allocation allowed anywhere).
// All of it is recomputed deterministically on every kernel_launch call.
// ---------------------------------------------------------------------------
__device__ uint8_t            g_sidx[CC][CC];   // [center a][sorted pos] -> cell
__device__ uint8_t            g_invp[CC][CC];   // [center a][cell]       -> sorted pos
__device__ float              g_base[CC][CC];   // [center a][sorted pos] -> base weight
__device__ unsigned long long g_mlo[CC][CC];    // angle mask bits 0..63   (i<j & ad<45)
__device__ unsigned long long g_mhi[CC][CC];    // angle mask bits 64..80
__device__ unsigned long long g_neglo[CC], g_neghi[CC];  // stones == -1, per center, sorted-pos bits
__device__ unsigned long long g_poslo[CC], g_poshi[CC];  // stones == +1
__device__ int                g_empty[CC];      // list of empty cells
__device__ int                g_nempty;

// ---------------------------------------------------------------------------
// Kernel 1: per-center geometry + board masks.
// grid = 81 blocks (one per center a), 128 threads.
// ---------------------------------------------------------------------------
__global__ void geom_kernel(const float* __restrict__ board) {
    __shared__ float   ang[CC];     // per-cell angle (unsorted)
    __shared__ float   sang[CC];    // angle at sorted position
    __shared__ int     key[CC];     // dsq*81 + cell : exact stable-sort key
    __shared__ uint8_t scell[CC];   // sorted pos -> cell
    __shared__ int8_t  sv[CC];      // board value per cell

    const int a = blockIdx.x;
    const int t = threadIdx.x;
    const int ay = a / 9, ax = a % 9;

    if (t < CC) {
        int cy = t / 9, cx = t % 9;
        int dy = cy - ay, dx = cx - ax;
        key[t] = (dy * dy + dx * dx) * CC + t;
        // Replicate: raw = atan2f32(-dy, dx) * f32(180/pi); angle = raw>0 ? raw : raw+360
        // atan2 computed in double then rounded -> correctly-rounded fp32 atan2.
        double da = ::atan2((double)(-dy), (double)dx);
        float raw = __fmul_rn((float)da, 57.295779513082323f);
        ang[t] = (raw > 0.0f) ? raw : __fadd_rn(raw, 360.0f);
        sv[t] = (int8_t)(int)board[t];
    }
    __syncthreads();

    if (t < CC) {
        // Stable rank by exact integer key (== jnp stable argsort of fp32 dist).
        const int mykey = key[t];
        int rank = 0;
        for (int m = 0; m < CC; m++) rank += (key[m] < mykey);
        g_sidx[a][rank] = (uint8_t)t;
        g_invp[a][t]    = (uint8_t)rank;
        scell[rank]     = (uint8_t)t;
        sang[rank]      = ang[t];
        // base = (max_dist - dist)/max_dist ; if < 0.5 scale by 0.5 — exact fp32 ops.
        float dist = __fsqrt_rn((float)(mykey / CC));
        float base = __fdiv_rn(__fsub_rn(12.727922061357855f, dist),
                               12.727922061357855f);
        if (base < 0.5f) base = __fmul_rn(base, 0.5f);
        g_base[a][rank] = base;
    }
    __syncthreads();

    if (t < CC) {
        // Angle mask for column j=t over rows i<j (sorted positions), ad<45 in fp32.
        const float aj = sang[t];
        unsigned long long lo = 0ull, hi = 0ull;
        for (int i = 0; i < t; i++) {
            float ad = fabsf(__fsub_rn(sang[i], aj));
            if (ad > 180.0f) ad = __fsub_rn(360.0f, ad);
            if (ad < 45.0f) {
                if (i < 64) lo |= 1ull << i;
                else        hi |= 1ull << (i - 64);
            }
        }
        g_mlo[a][t] = lo;
        g_mhi[a][t] = hi;
    }

    if (t == 0) {
        // Stone masks in sorted-position space for this center.
        unsigned long long nlo = 0ull, nhi = 0ull, plo = 0ull, phi = 0ull;
        for (int p = 0; p < CC; p++) {
            int v = sv[scell[p]];
            if (v < 0) { if (p < 64) nlo |= 1ull << p; else nhi |= 1ull << (p - 64); }
            else if (v > 0) { if (p < 64) plo |= 1ull << p; else phi |= 1ull << (p - 64); }
        }
        g_neglo[a] = nlo; g_neghi[a] = nhi;
        g_poslo[a] = plo; g_poshi[a] = phi;
        if (a == 0) {
            int n = 0;
            for (int c = 0; c < CC; c++) if (sv[c] == 0) g_empty[n++] = c;
            g_nempty = n;
        }
    }
}

// ---------------------------------------------------------------------------
// Kernel 2: one block per candidate cell b. Accumulates
//   total[b] = sum over empty a != b, sum over sorted pos j with s_j != 0 of
//              base[a][j] * 2^{-k} * s_j,
//   k = popcount(angle_mask[a][j] & opposite_stone_mask)
// where the hypothetical stone at b adds a +1 bit at position invp[a][b].
// ---------------------------------------------------------------------------
__global__ void main_kernel(const float* __restrict__ board,
                            float* __restrict__ out) {
    const int b = blockIdx.x;
    const int t = threadIdx.x;

    __shared__ int8_t bvi[CC];
    __shared__ unsigned long long pblo[CC], pbhi[CC];  // pos-mask with b's bit, per center a
    __shared__ float wsum[4];

    if (t < CC) bvi[t] = (int8_t)(int)board[t];
    __syncthreads();

    if (bvi[b] != 0) {           // non-empty candidate -> output exactly 0
        if (t == 0) out[b] = 0.0f;
        return;
    }

    if (t < CC) {
        int p = g_invp[t][b];    // sorted position of cell b at center t
        unsigned long long lo = g_poslo[t], hi = g_poshi[t];
        if (p < 64) lo |= 1ull << p; else hi |= 1ull << (p - 64);
        pblo[t] = lo; pbhi[t] = hi;
    }
    __syncthreads();

    const int nE = g_nempty;
    const int total = nE * CC;
    float acc = 0.0f;

    for (int slot = t; slot < total; slot += blockDim.x) {
        int ai = slot / CC;
        int j  = slot - ai * CC;
        int a  = g_empty[ai];
        if (a == b) continue;                      // boardp[b,a] = 1 -> masked out
        int cell = g_sidx[a][j];
        int s = (int)bvi[cell] + (cell == b ? 1 : 0);
        if (s == 0) continue;
        unsigned long long olo, ohi;
        if (s > 0) { olo = g_neglo[a]; ohi = g_neghi[a]; }
        else       { olo = pblo[a];    ohi = pbhi[a];    }
        int k = __popcll(g_mlo[a][j] & olo) + __popcll(g_mhi[a][j] & ohi);
        acc += g_base[a][j] * exp2f(-(float)k) * (float)s;
    }

    // Block reduction (128 threads = 4 warps).
    for (int o = 16; o; o >>= 1) acc += __shfl_down_sync(0xffffffffu, acc, o);
    if ((t & 31) == 0) wsum[t >> 5] = acc;
    __syncthreads();
    if (t == 0) out[b] = wsum[0] + wsum[1] + wsum[2] + wsum[3];
}

// ---------------------------------------------------------------------------
// kernel_launch: graph-capturable, allocation-free, deterministic.
// Inputs (metadata order): all_coords int32[243], board float32[81].
// We only need the board; pick it by element count for robustness.
// ---------------------------------------------------------------------------
extern "C" void kernel_launch(void* const* d_in, const int* in_sizes, int n_in,
                              void* d_out, int out_size) {
    const float* board = nullptr;
    for (int i = 0; i < n_in; i++) {
        if (in_sizes[i] == 81) { board = (const float*)d_in[i]; break; }
    }
    if (!board) board = (const float*)d_in[n_in - 1];

    geom_kernel<<<81, 128>>>(board);
    main_kernel<<<81, 128>>>(board, (float*)d_out);
}

// round 2
// speedup vs baseline: 1.8265x; 1.8265x over previous
#include <cuda_runtime.h>
#include <cstdint>
#include <math.h>

// Problem constants: N=9 board, C=81 cells.
#define CC 81

// ---------------------------------------------------------------------------
// Fused kernel: one block per center cell a (only empty centers do work).
// All geometry (stable sort order, base weights, 45-degree angle masks) is
// computed block-locally in shared memory — bit-identical to round-1 pipeline.
//
// For empty center a, contribution to empty candidate b (b != a):
//   contrib = C0 + 0.5*T(p_b) + selfT[p_b]
// where
//   C0  = P - S
//   P   = sum over +1 stones j of base[j]*2^-kneg(j)
//   S   = sum over -1 stones j of base[j]*2^-kpos(j)
//   T(p)= sum over -1 stones j with bit p set in angle mask A_j of negT[j]
//   selfT[p] = base[p]*2^-kneg(p)   (the hypothetical +1 stone at b itself)
// Accumulated into out[] with atomicAdd; out[] zeroed by cudaMemsetAsync.
// ---------------------------------------------------------------------------
__global__ void __launch_bounds__(96) fused_kernel(const float* __restrict__ board,
                                                   float* __restrict__ out) {
    __shared__ float   ang[CC], sang[CC], base_s[CC];
    __shared__ float   negT[CC], selfT[CC], contribP[CC];
    __shared__ int     key[CC];
    __shared__ unsigned long long mlo[CC], mhi[CC];
    __shared__ signed char bv[CC];     // board value per cell
    __shared__ signed char sv[CC];     // board value per sorted position
    __shared__ unsigned char rankof[CC];
    __shared__ unsigned char negList[CC];
    __shared__ int   negCnt;
    __shared__ unsigned long long neglo, neghi, poslo, poshi;
    __shared__ float C0;

    const int a = blockIdx.x;
    const int t = threadIdx.x;

    if (t < CC) bv[t] = (signed char)(int)board[t];
    __syncthreads();
    if (bv[a] != 0) return;            // non-empty center contributes nothing

    const int ay = a / 9, ax = a % 9;
    if (t < CC) {
        int cy = t / 9, cx = t % 9;
        int dy = cy - ay, dx = cx - ax;
        key[t] = (dy * dy + dx * dx) * CC + t;   // exact stable-argsort key
        // Bit-identical to round-1: correctly-rounded fp32 atan2 via double.
        double da = ::atan2((double)(-dy), (double)dx);
        float raw = __fmul_rn((float)da, 57.295779513082323f);
        ang[t] = (raw > 0.0f) ? raw : __fadd_rn(raw, 360.0f);
    }
    __syncthreads();

    if (t < CC) {
        const int myk = key[t];
        int r = 0;
        #pragma unroll 9
        for (int m = 0; m < CC; m++) r += (key[m] < myk);
        rankof[t] = (unsigned char)r;
        sang[r]   = ang[t];
        sv[r]     = bv[t];
        float dist = __fsqrt_rn((float)(myk / CC));
        float b_ = __fdiv_rn(__fsub_rn(12.727922061357855f, dist),
                             12.727922061357855f);
        if (b_ < 0.5f) b_ = __fmul_rn(b_, 0.5f);
        base_s[r] = b_;
    }
    __syncthreads();

    if (t < CC) {
        // Angle mask A_t over rows i < t (sorted positions), ad < 45 in fp32.
        const float aj = sang[t];
        unsigned long long lo = 0ull, hi = 0ull;
        for (int i = 0; i < t; i++) {
            float ad = fabsf(__fsub_rn(sang[i], aj));
            if (ad > 180.0f) ad = __fsub_rn(360.0f, ad);
            if (ad < 45.0f) {
                if (i < 64) lo |= 1ull << i;
                else        hi |= 1ull << (i - 64);
            }
        }
        mlo[t] = lo;
        mhi[t] = hi;
    }
    if (t == 0) {
        unsigned long long nlo = 0ull, nhi = 0ull, plo = 0ull, phi = 0ull;
        int nc = 0;
        for (int p = 0; p < CC; p++) {
            int v = sv[p];
            if (v < 0) {
                if (p < 64) nlo |= 1ull << p; else nhi |= 1ull << (p - 64);
                negList[nc++] = (unsigned char)p;
            } else if (v > 0) {
                if (p < 64) plo |= 1ull << p; else phi |= 1ull << (p - 64);
            }
        }
        neglo = nlo; neghi = nhi; poslo = plo; poshi = phi; negCnt = nc;
    }
    __syncthreads();

    if (t < CC) {
        int kneg = __popcll(mlo[t] & neglo) + __popcll(mhi[t] & neghi);
        float st = base_s[t] * exp2f(-(float)kneg);
        selfT[t] = st;
        contribP[t] = (sv[t] > 0) ? st : 0.0f;
        float nt = 0.0f;
        if (sv[t] < 0) {
            int kpos = __popcll(mlo[t] & poslo) + __popcll(mhi[t] & poshi);
            nt = base_s[t] * exp2f(-(float)kpos);
        }
        negT[t] = nt;
    }
    __syncthreads();

    if (t == 0) {
        float P = 0.0f, S = 0.0f;
        for (int j = 0; j < CC; j++) { P += contribP[j]; S += negT[j]; }
        C0 = P - S;
    }
    __syncthreads();

    if (t < CC && bv[t] == 0 && t != a) {
        const int p = (int)rankof[t];
        float Tb = 0.0f;
        const int nc = negCnt;
        for (int q = 0; q < nc; q++) {
            int j = (int)negList[q];
            bool bit = (p < 64) ? ((mlo[j] >> p) & 1ull)
                                : ((mhi[j] >> (p - 64)) & 1ull);
            if (bit) Tb += negT[j];
        }
        atomicAdd(&out[t], C0 + 0.5f * Tb + selfT[p]);
    }
}

// ---------------------------------------------------------------------------
// kernel_launch: graph-capturable, allocation-free, deterministic.
// Inputs (metadata order): all_coords int32[243], board float32[81].
// ---------------------------------------------------------------------------
extern "C" void kernel_launch(void* const* d_in, const int* in_sizes, int n_in,
                              void* d_out, int out_size) {
    const float* board = nullptr;
    for (int i = 0; i < n_in; i++) {
        if (in_sizes[i] == 81) { board = (const float*)d_in[i]; break; }
    }
    if (!board) board = (const float*)d_in[n_in - 1];

    cudaMemsetAsync(d_out, 0, 81 * sizeof(float));
    fused_kernel<<<81, 96>>>(board, (float*)d_out);
}

// round 3
// speedup vs baseline: 2.2933x; 1.2556x over previous
#include <cuda_runtime.h>
#include <cstdint>
#include <math.h>

// Problem constants: N=9 board, C=81 cells.
#define CC 81

// ===========================================================================
// Compile-time angle table: ang[(dy+8)*17 + (dx+8)] for dy,dx in [-8,8],
// replicating EXACTLY the runtime pipeline used by the round-1/2 kernels:
//   da   = atan2<double>(-dy, dx)            (correctly rounded to ~1e-15)
//   raw  = f32(da) * f32(180/pi)             (fp32 round-to-nearest)
//   ang  = raw > 0 ? raw : raw + 360.0f      (fp32)
// The constexpr atan2 agrees with libdevice's to ~1e-15 relative, so the
// fp32-rounded results are identical except on half-ulp double ties
// (probability ~2^-29 per entry) — the 45-degree boundary decisions that set
// rel_err are unchanged.
// ===========================================================================
constexpr double CPI = 3.14159265358979323846264338327950288;

constexpr double c_sqrt(double x) {
    double g = (x < 1.0) ? 1.0 : x;
    for (int i = 0; i < 48; i++) g = 0.5 * (g + x / g);
    return g;
}

// atan for z in [0,1]: three half-angle reductions -> |r| <= 0.0985, then Taylor.
constexpr double c_atan01(double z) {
    double r = z;
    for (int i = 0; i < 3; i++) r = r / (1.0 + c_sqrt(1.0 + r * r));
    double r2 = r * r, s = 0.0, term = r;
    for (int k = 0; k < 13; k++) {
        s += ((k & 1) ? -term : term) / (double)(2 * k + 1);
        term *= r2;
    }
    return 8.0 * s;
}

constexpr double c_atan2(double y, double x) {
    if (x == 0.0) {
        if (y > 0.0) return  CPI * 0.5;
        if (y < 0.0) return -CPI * 0.5;
        return 0.0;
    }
    double ay = (y < 0.0) ? -y : y;
    double ax = (x < 0.0) ? -x : x;
    double az = ay / ax;
    double a  = (az <= 1.0) ? c_atan01(az) : (CPI * 0.5 - c_atan01(1.0 / az));
    if (x < 0.0) a = CPI - a;
    return (y < 0.0) ? -a : a;
}

struct AngTable { float v[289]; };

constexpr AngTable make_ang() {
    AngTable tb{};
    for (int dy = -8; dy <= 8; dy++)
        for (int dx = -8; dx <= 8; dx++) {
            double da = c_atan2((double)(-dy), (double)dx);
            float raw = (float)da * 57.295779513082323f;   // fp32 RN mult
            tb.v[(dy + 8) * 17 + (dx + 8)] = (raw > 0.0f) ? raw : raw + 360.0f;
        }
    return tb;
}

__constant__ AngTable d_ang = make_ang();

// ===========================================================================
// Fused kernel: one block per center cell a (empty centers only do work).
// Per empty center a, contribution to empty candidate b != a:
//   contrib = C0 + 0.5*T(p_b) + selfT[p_b]
// C0 = sum_j (contribP_j - negT_j);  T(p) = sum over -1 stones j with angle
// mask bit p of negT[j];  selfT[p] = base[p]*2^-kneg(p).
// out[] zeroed by cudaMemsetAsync, accumulated with atomicAdd.
// ===========================================================================
__global__ void __launch_bounds__(96) fused_kernel(const float* __restrict__ board,
                                                   float* __restrict__ out) {
    __shared__ float   sang[CC], base_s[CC], negT[CC], selfT[CC];
    __shared__ int     key[CC];
    __shared__ unsigned long long mlo[CC], mhi[CC];
    __shared__ signed char bv[CC];     // board value per cell
    __shared__ signed char sv[CC];     // board value per sorted position
    __shared__ unsigned char rankof[CC];
    __shared__ unsigned long long stmask[4];  // [0]=neg lo [1]=neg hi [2]=pos lo [3]=pos hi
    __shared__ float warpsum[3];

    const int a = blockIdx.x;
    const int t = threadIdx.x;

    if (t < CC) bv[t] = (signed char)(int)board[t];
    if (t < 4)  stmask[t] = 0ull;
    __syncthreads();
    if (bv[a] != 0) return;            // non-empty center contributes nothing

    const int ay = a / 9, ax = a % 9;
    int   myk = 0;
    float myang = 0.0f;
    if (t < CC) {
        int cy = t / 9, cx = t % 9;
        int dy = cy - ay, dx = cx - ax;
        myk = (dy * dy + dx * dx) * CC + t;      // exact stable-argsort key
        key[t] = myk;
        myang = d_ang.v[(dy + 8) * 17 + (dx + 8)];
    }
    __syncthreads();

    if (t < CC) {
        int r = 0;
        #pragma unroll 9
        for (int m = 0; m < CC; m++) r += (key[m] < myk);
        rankof[t] = (unsigned char)r;
        sang[r]   = myang;
        sv[r]     = bv[t];
        float dist = __fsqrt_rn((float)(myk / CC));
        float b_ = __fdiv_rn(__fsub_rn(12.727922061357855f, dist),
                             12.727922061357855f);
        if (b_ < 0.5f) b_ = __fmul_rn(b_, 0.5f);
        base_s[r] = b_;
        int v = bv[t];
        if (v != 0) {
            int idx = (v < 0 ? 0 : 2) + (r >= 64 ? 1 : 0);
            atomicOr(&stmask[idx], 1ull << (r & 63));
        }
    }
    __syncthreads();

    float cval = 0.0f;                 // contribP - negT for this sorted pos
    if (t < CC) {
        // Angle mask A_t over rows i < t (sorted positions), ad < 45 in fp32.
        const float aj = sang[t];
        unsigned long long lo = 0ull, hi = 0ull;
        for (int i = 0; i < t; i++) {
            float ad = fabsf(__fsub_rn(sang[i], aj));
            if (ad > 180.0f) ad = __fsub_rn(360.0f, ad);
            if (ad < 45.0f) {
                if (i < 64) lo |= 1ull << i;
                else        hi |= 1ull << (i - 64);
            }
        }
        mlo[t] = lo;
        mhi[t] = hi;
        int kneg = __popcll(lo & stmask[0]) + __popcll(hi & stmask[1]);
        float st = base_s[t] * exp2f(-(float)kneg);
        selfT[t] = st;
        float nt = 0.0f;
        if (sv[t] < 0) {
            int kpos = __popcll(lo & stmask[2]) + __popcll(hi & stmask[3]);
            nt = base_s[t] * exp2f(-(float)kpos);
        }
        negT[t] = nt;
        cval = ((sv[t] > 0) ? st : 0.0f) - nt;
    }

    // C0 = sum over j of cval  (3 warps of the 96-thread block)
    for (int o = 16; o; o >>= 1) cval += __shfl_down_sync(0xffffffffu, cval, o);
    if ((t & 31) == 0) warpsum[t >> 5] = cval;
    __syncthreads();                   // also publishes mlo/mhi/negT/selfT
    const float C0 = warpsum[0] + warpsum[1] + warpsum[2];

    if (t < CC && bv[t] == 0 && t != a) {
        const int p = (int)rankof[t];
        const unsigned long long pm_lo = (p < 64) ? (1ull << p) : 0ull;
        const unsigned long long pm_hi = (p < 64) ? 0ull : (1ull << (p - 64));
        float Tb = 0.0f;
        #pragma unroll 3
        for (int j = 0; j < CC; j++) {
            if ((mlo[j] & pm_lo) | (mhi[j] & pm_hi)) Tb += negT[j];
        }
        atomicAdd(&out[t], C0 + 0.5f * Tb + selfT[p]);
    }
}

// ---------------------------------------------------------------------------
// kernel_launch: graph-capturable, allocation-free, deterministic.
// Inputs (metadata order): all_coords int32[243], board float32[81].
// ---------------------------------------------------------------------------
extern "C" void kernel_launch(void* const* d_in, const int* in_sizes, int n_in,
                              void* d_out, int out_size) {
    const float* board = nullptr;
    for (int i = 0; i < n_in; i++) {
        if (in_sizes[i] == 81) { board = (const float*)d_in[i]; break; }
    }
    if (!board) board = (const float*)d_in[n_in - 1];

    cudaMemsetAsync(d_out, 0, 81 * sizeof(float));
    fused_kernel<<<81, 96>>>(board, (float*)d_out);
}

// round 6
// speedup vs baseline: 3.5222x; 1.5358x over previous
#include <cuda_runtime.h>
#include <cstdint>
#include <math.h>

// Problem constants: N=9 board, C=81 cells.
#define CC 81
#define ND 17            // dy,dx in [-8,8]
#define NDIR (ND*ND)     // 289 distinct direction vectors

// ===========================================================================
// Compile-time geometry. Replicates EXACTLY the fp32 decision pipeline of the
// verified round-2/3 kernels:
//   angle: da = atan2<double>(-dy,dx); raw = f32(da)*f32(180/pi);
//          ang = raw>0 ? raw : raw+360.0f                    (fp32 RN)
//   stable order: integer key dsq*81 + cell  (== stable argsort of fp32 dist)
//   base: dist=f32(sqrt(dsq)); b=(maxd-dist)/maxd; if (b<0.5f) b*=0.5f (fp32)
//   mask bit (i<j sorted): ad=|ang_i-ang_j| (wrap >180 -> 360-ad); ad < 45.0f
// Constant-evaluation float arithmetic is IEEE fp32 RN (EDG frontend, not
// affected by device fast-math), so the decision set is identical to the
// runtime pipeline that measured rel_err = 8.35e-4.
// ===========================================================================
constexpr double CPI = 3.14159265358979323846264338327950288;

constexpr double c_sqrt(double x) {
    if (x <= 0.0) return 0.0;
    double g = (x < 1.0) ? 1.0 : x;
    for (int i = 0; i < 30; i++) g = 0.5 * (g + x / g);
    return g;
}
constexpr double c_atan01(double z) {
    double r = z;
    for (int i = 0; i < 3; i++) r = r / (1.0 + c_sqrt(1.0 + r * r));
    double r2 = r * r, s = 0.0, term = r;
    for (int k = 0; k < 13; k++) {
        s += ((k & 1) ? -term : term) / (double)(2 * k + 1);
        term *= r2;
    }
    return 8.0 * s;
}
constexpr double c_atan2(double y, double x) {
    if (x == 0.0) return (y > 0.0) ? CPI * 0.5 : (y < 0.0 ? -CPI * 0.5 : 0.0);
    double ay = (y < 0.0) ? -y : y, ax = (x < 0.0) ? -x : x;
    double az = ay / ax;
    double a  = (az <= 1.0) ? c_atan01(az) : (CPI * 0.5 - c_atan01(1.0 / az));
    if (x < 0.0) a = CPI - a;
    return (y < 0.0) ? -a : a;
}

struct Tables {
    unsigned long long mlo[CC][CC];  // [a][sorted j]: bits i<j  (i in 0..63)
    unsigned long long mhi[CC][CC];  // [a][sorted j]: bits i-64
    unsigned long long tlo[CC][CC];  // [a][cell c]: bit j iff mask[a][j] has bit rank(c)
    unsigned long long thi[CC][CC];
    float              base[CC][CC]; // [a][sorted j]
    unsigned char      rank[CC][CC]; // [a][cell] -> sorted pos
};

constexpr Tables make_tables() {
    Tables tb{};
    // Per-direction fp32 angle, index (dy+8)*17 + (dx+8).
    float angt[NDIR] = {};
    for (int dy = -8; dy <= 8; dy++)
        for (int dx = -8; dx <= 8; dx++) {
            double da = c_atan2((double)(-dy), (double)dx);
            float raw = (float)da * 57.295779513082323f;
            angt[(dy + 8) * ND + (dx + 8)] = (raw > 0.0f) ? raw : raw + 360.0f;
        }
    // Direction-pair 45-degree adjacency, packed 289 bits -> 5 u64 per row.
    // (automatic storage — 'static' here would make the function non-constexpr)
    unsigned long long adj[NDIR][5] = {};
    for (int u = 0; u < NDIR; u++)
        for (int v = 0; v < NDIR; v++) {
            float ad = angt[u] - angt[v];
            if (ad < 0.0f) ad = -ad;
            if (ad > 180.0f) ad = 360.0f - ad;
            if (ad < 45.0f) adj[u][v >> 6] |= 1ull << (v & 63);
        }
    for (int a = 0; a < CC; a++) {
        int ay = a / 9, ax = a % 9;
        int dsq[CC] = {}, dir[CC] = {};
        for (int c = 0; c < CC; c++) {
            int dy = c / 9 - ay, dx = c % 9 - ax;
            dsq[c] = dy * dy + dx * dx;
            dir[c] = (dy + 8) * ND + (dx + 8);
        }
        // Counting sort on dsq (<=128), ties by ascending cell index ==
        // stable argsort of the integer key dsq*81 + c.
        int start[130] = {};
        for (int c = 0; c < CC; c++) start[dsq[c] + 1]++;
        for (int d = 0; d < 129; d++) start[d + 1] += start[d];
        int sidx[CC] = {}, sdir[CC] = {};
        for (int c = 0; c < CC; c++) {
            int r = start[dsq[c]]++;
            tb.rank[a][c] = (unsigned char)r;
            sidx[r] = c;
            sdir[r] = dir[c];
            float dist = (float)c_sqrt((double)dsq[c]);
            float b_ = (12.727922061357855f - dist) / 12.727922061357855f;
            if (b_ < 0.5f) b_ = b_ * 0.5f;
            tb.base[a][r] = b_;
        }
        for (int j = 0; j < CC; j++) {
            const unsigned long long* row = adj[sdir[j]];
            for (int i = 0; i < j; i++) {
                int v = sdir[i];
                if ((row[v >> 6] >> (v & 63)) & 1ull) {
                    if (i < 64) tb.mlo[a][j] |= 1ull << i;
                    else        tb.mhi[a][j] |= 1ull << (i - 64);
                    int c = sidx[i];
                    if (j < 64) tb.tlo[a][c] |= 1ull << j;
                    else        tb.thi[a][c] |= 1ull << (j - 64);
                }
            }
        }
    }
    return tb;
}

// constexpr forces constant initialization (no dynamic init for __device__).
__device__ constexpr Tables d_tab = make_tables();

// ===========================================================================
// Fused kernel: one block per center a (empty centers only).
// Contribution of center a to empty candidate b != a:
//   contrib = C0 + 0.5*T(b) + selfT[rank(b)]
// C0 = sum_j(contribP_j - negT_j); negT/selfT from popcounts of compile-time
// masks with runtime stone bitmasks; T(b) = sum over neg-stone positions j in
// the transposed mask of b of negT[j].
// out[] zeroed by cudaMemsetAsync, accumulated with atomicAdd.
// ===========================================================================
__global__ void __launch_bounds__(96) fused_kernel(const float* __restrict__ board,
                                                   float* __restrict__ out) {
    __shared__ float negT[CC], selfT[CC];
    __shared__ unsigned long long stmask[4]; // [0]=neg lo [1]=neg hi [2]=pos lo [3]=pos hi
    __shared__ float warpsum[3];
    __shared__ signed char bv[CC];

    const int a = blockIdx.x;
    const int t = threadIdx.x;

    // Independent prefetches — all issued before any barrier/dependency.
    unsigned long long Mlo = 0, Mhi = 0, Tlo = 0, Thi = 0;
    float bs = 0.0f;
    int   r  = 0;
    if (t < CC) {
        Mlo = d_tab.mlo[a][t];  Mhi = d_tab.mhi[a][t];   // mask of sorted pos j=t
        Tlo = d_tab.tlo[a][t];  Thi = d_tab.thi[a][t];   // trans mask of cell b=t
        bs  = d_tab.base[a][t];
        r   = (int)d_tab.rank[a][t];                     // sorted pos of cell t
        bv[t] = (signed char)(int)board[t];
    }
    if (t < 4) stmask[t] = 0ull;
    __syncthreads();

    if (bv[a] != 0) return;            // non-empty center: contributes nothing

    if (t < CC) {
        int v = (int)bv[t];
        if (v != 0)
            atomicOr(&stmask[(v < 0 ? 0 : 2) + (r >= 64)], 1ull << (r & 63));
    }
    __syncthreads();

    const unsigned long long nLo = stmask[0], nHi = stmask[1];
    const unsigned long long pLo = stmask[2], pHi = stmask[3];

    float cval = 0.0f;
    if (t < CC) {
        // Occupancy of sorted position t, recovered from the stone bitmasks.
        bool isneg = (t < 64) ? ((nLo >> t) & 1ull) : ((nHi >> (t - 64)) & 1ull);
        bool ispos = (t < 64) ? ((pLo >> t) & 1ull) : ((pHi >> (t - 64)) & 1ull);
        int kneg = __popcll(Mlo & nLo) + __popcll(Mhi & nHi);
        float st = bs * exp2f(-(float)kneg);
        selfT[t] = st;
        float nt = 0.0f;
        if (isneg) {
            int kpos = __popcll(Mlo & pLo) + __popcll(Mhi & pHi);
            nt = bs * exp2f(-(float)kpos);
        }
        negT[t] = nt;
        cval = (ispos ? st : 0.0f) - nt;
    }

    // C0 reduction over the 3 warps (threads >= 81 contribute 0).
    for (int o = 16; o; o >>= 1) cval += __shfl_down_sync(0xffffffffu, cval, o);
    if ((t & 31) == 0) warpsum[t >> 5] = cval;
    __syncthreads();                   // also publishes negT / selfT
    const float C0 = warpsum[0] + warpsum[1] + warpsum[2];

    if (t < CC && bv[t] == 0 && t != a) {
        float Tb = 0.0f;
        unsigned long long m = Tlo & nLo;        // ascending-j order == round 3
        while (m)  { int j = __ffsll((long long)m)  - 1; Tb += negT[j];      m  &= m  - 1; }
        unsigned long long m2 = Thi & nHi;
        while (m2) { int j = __ffsll((long long)m2) - 1; Tb += negT[j + 64]; m2 &= m2 - 1; }
        atomicAdd(&out[t], C0 + 0.5f * Tb + selfT[r]);
    }
}

// ---------------------------------------------------------------------------
// kernel_launch: graph-capturable, allocation-free, deterministic.
// Inputs (metadata order): all_coords int32[243], board float32[81].
// ---------------------------------------------------------------------------
extern "C" void kernel_launch(void* const* d_in, const int* in_sizes, int n_in,
                              void* d_out, int out_size) {
    const float* board = nullptr;
    for (int i = 0; i < n_in; i++) {
        if (in_sizes[i] == 81) { board = (const float*)d_in[i]; break; }
    }
    if (!board) board = (const float*)d_in[n_in - 1];

    cudaMemsetAsync(d_out, 0, 81 * sizeof(float));
    fused_kernel<<<81, 96>>>(board, (float*)d_out);
}